// round 7
// baseline (speedup 1.0000x reference)
#include <cuda_runtime.h>
#include <cuda_bf16.h>
#include <cstdint>

#define BSZ 4096
#define DIM 1024
#define NSCALE 3
#define BM 128
#define BN 128
#define NBT (BSZ / BN)      // 32 column tiles
#define KSB 64              // int8 K elements (=bytes) per row per stage
#define KT (DIM / KSB)      // 16 k-stages
#define NST 4               // smem pipeline stages
#define PITCH 80            // bytes per smem row (64 data + 16 pad) -> conflict-free ldmatrix
#define STAGE_B (BM * PITCH)                // 10240 bytes per tile per stage
#define SMEM_DYN (2 * NST * STAGE_B)        // 81920

// ---------------- scratch (static device globals; no allocation) ----------------
__device__ int8_t g_A8[BSZ * DIM];
__device__ int8_t g_P8[NSCALE][BSZ * DIM];
__device__ float g_qa[BSZ];                 // dequant scale for A rows
__device__ float g_qb[NSCALE][BSZ];         // dequant scale for P rows
__device__ float g_invt[NSCALE][BSZ];
__device__ float g_partial[NSCALE][NBT][BSZ];
__device__ float g_diag[NSCALE][BSZ];

struct Ptrs {
    const float* anchor;
    const int*   index;
    const int*   i2c[3];
    const float* cent[3];
    const float* dens[3];
};

// ---------------- PTX helpers ----------------
__device__ __forceinline__ uint32_t smem_u32(const void* p) {
    uint32_t a;
    asm("{ .reg .u64 t; cvta.to.shared.u64 t, %1; cvt.u32.u64 %0, t; }" : "=r"(a) : "l"(p));
    return a;
}
__device__ __forceinline__ void ldm_x4(uint32_t r[4], uint32_t addr) {
    asm volatile("ldmatrix.sync.aligned.m8n8.x4.shared.b16 {%0,%1,%2,%3}, [%4];\n"
                 : "=r"(r[0]), "=r"(r[1]), "=r"(r[2]), "=r"(r[3]) : "r"(addr));
}
__device__ __forceinline__ void mma_s8(int c[4], const uint32_t a[4], const uint32_t b[2]) {
    asm volatile("mma.sync.aligned.m16n8k32.row.col.s32.s8.s8.s32 "
                 "{%0,%1,%2,%3}, {%4,%5,%6,%7}, {%8,%9}, {%0,%1,%2,%3};\n"
                 : "+r"(c[0]), "+r"(c[1]), "+r"(c[2]), "+r"(c[3])
                 : "r"(a[0]), "r"(a[1]), "r"(a[2]), "r"(a[3]), "r"(b[0]), "r"(b[1]));
}
__device__ __forceinline__ void cp16_s(uint32_t saddr, const void* gmem) {
    asm volatile("cp.async.cg.shared.global [%0], [%1], 16;\n" :: "r"(saddr), "l"(gmem));
}

// ---------------- prep: warp-per-row normalize + int8 quantize ----------------
__global__ __launch_bounds__(256) void prep_kernel(Ptrs p) {
    int w = blockIdx.x * 8 + (threadIdx.x >> 5);
    int lane = threadIdx.x & 31;

    const float* src;
    int8_t* dst;
    float* qout;
    int qidx;
    if (w < BSZ) {
        src = p.anchor + (size_t)w * DIM;
        dst = g_A8 + (size_t)w * DIM;
        qout = g_qa; qidx = w;
    } else {
        int s = (w - BSZ) >> 12;
        int j = (w - BSZ) & (BSZ - 1);
        int cid = p.i2c[s][p.index[j]];
        src = p.cent[s] + (size_t)cid * DIM;
        dst = g_P8[s] + (size_t)j * DIM;
        qout = g_qb[s]; qidx = j;
        if (lane == 0) g_invt[s][j] = 1.0f / p.dens[s][cid];
    }

    float4 x[8];
    const float4* s4 = (const float4*)src;
    #pragma unroll
    for (int k = 0; k < 8; k++) x[k] = s4[lane + 32 * k];

    float ss = 0.f, mx = 0.f;
    #pragma unroll
    for (int k = 0; k < 8; k++) {
        ss += x[k].x * x[k].x + x[k].y * x[k].y + x[k].z * x[k].z + x[k].w * x[k].w;
        mx = fmaxf(mx, fmaxf(fmaxf(fabsf(x[k].x), fabsf(x[k].y)), fmaxf(fabsf(x[k].z), fabsf(x[k].w))));
    }
    #pragma unroll
    for (int o = 16; o > 0; o >>= 1) {
        ss += __shfl_xor_sync(0xffffffffu, ss, o);
        mx = fmaxf(mx, __shfl_xor_sync(0xffffffffu, mx, o));
    }
    float r = rsqrtf(fmaxf(ss, 1e-24f));
    float am = mx * r;                       // absmax of normalized row
    float qs = 127.0f / am;                  // quantize scale
    if (lane == 0) qout[qidx] = am * (1.0f / 127.0f);

    char4* d4 = (char4*)dst;
    #pragma unroll
    for (int k = 0; k < 8; k++) {
        char4 c;
        c.x = (char)__float2int_rn(x[k].x * r * qs);
        c.y = (char)__float2int_rn(x[k].y * r * qs);
        c.z = (char)__float2int_rn(x[k].z * r * qs);
        c.w = (char)__float2int_rn(x[k].w * r * qs);
        d4[lane + 32 * k] = c;
    }
}

// ---------------- fused int8 GEMM (S = A @ P^T) + exp epilogue ----------------
__global__ __launch_bounds__(256) void gemm_kernel() {
    extern __shared__ char dynsmem[];
    const int scale = blockIdx.z;
    const int bm = blockIdx.y, bn = blockIdx.x;
    const int tid = threadIdx.x;
    const int lane = tid & 31;
    const int warp = tid >> 5;
    const int wm = warp >> 2;     // 0..1 : 64 rows each
    const int wn = warp & 3;      // 0..3 : 32 cols each

    __shared__ float sred[BM][4];
    __shared__ float s_wlo[BN];   // qb[c] * invt[c+1]  (used when gj < gi)
    __shared__ float s_whi[BN];   // qb[c] * invt[c]    (used when gj > gi)
    __shared__ float s_qb[BN];
    __shared__ float s_qa[BM];
    __shared__ float s_invt0;

    const uint32_t sAb = smem_u32(dynsmem);
    const uint32_t sBb = sAb + NST * STAGE_B;

    const int8_t* gA = g_A8 + (size_t)(bm * BM) * DIM;
    const int8_t* gB = g_P8[scale] + (size_t)(bn * BN) * DIM;
    const float* invt = g_invt[scale];
    const int rowBase = bm * BM, colBase = bn * BN;

    if (tid < BN) {
        int idx = colBase + tid;
        float qb = g_qb[scale][idx];
        float ic = invt[idx];
        float in = invt[idx + 1 > BSZ - 1 ? BSZ - 1 : idx + 1];
        s_qb[tid] = qb;
        s_whi[tid] = qb * ic;
        s_wlo[tid] = qb * in;
    } else if (tid < 2 * BN) {
        s_qa[tid - BN] = g_qa[rowBase + tid - BN];
    }
    if (tid == 0) s_invt0 = invt[0];

    int acc[4][4][4];
    #pragma unroll
    for (int a = 0; a < 4; a++)
        #pragma unroll
        for (int b = 0; b < 4; b++)
            #pragma unroll
            for (int c = 0; c < 4; c++) acc[a][b][c] = 0;

    // ---- stage loader: 2x (A,B) 16B cp.async per thread per stage ----
    auto load_stage = [&](int buf, int kt) {
        uint32_t sa = sAb + buf * STAGE_B;
        uint32_t sb = sBb + buf * STAGE_B;
        const int8_t* pA = gA + kt * KSB;
        const int8_t* pB = gB + kt * KSB;
        #pragma unroll
        for (int r = 0; r < 2; r++) {
            int q = tid + 256 * r;
            int row = q >> 2, ch = q & 3;
            uint32_t off = (uint32_t)(row * PITCH + ch * 16);
            cp16_s(sa + off, pA + (size_t)row * DIM + ch * 16);
            cp16_s(sb + off, pB + (size_t)row * DIM + ch * 16);
        }
        asm volatile("cp.async.commit_group;\n");
    };

    // ---- fragment loaders (kk = byte offset of k32 step: 0 or 32) ----
    auto ldA = [&](int buf, int kk, uint32_t af[4][4]) {
        #pragma unroll
        for (int mb = 0; mb < 4; mb++) {
            int row = wm * 64 + mb * 16 + (lane & 15);
            int ko = kk + ((lane & 16) ? 16 : 0);
            ldm_x4(af[mb], sAb + buf * STAGE_B + row * PITCH + ko);
        }
    };
    auto ldB = [&](int buf, int kk, uint32_t bfr[4][2]) {
        #pragma unroll
        for (int nbp = 0; nbp < 2; nbp++) {
            int row = wn * 32 + nbp * 16 + (lane & 7) + ((lane & 16) ? 8 : 0);
            int ko = kk + ((lane & 8) ? 16 : 0);
            uint32_t t[4];
            ldm_x4(t, sBb + buf * STAGE_B + row * PITCH + ko);
            bfr[nbp * 2][0] = t[0]; bfr[nbp * 2][1] = t[1];
            bfr[nbp * 2 + 1][0] = t[2]; bfr[nbp * 2 + 1][1] = t[3];
        }
    };

    uint32_t af[2][4][4], bf[2][4][2];

    // prologue: fill 3 of 4 stages
    load_stage(0, 0); load_stage(1, 1); load_stage(2, 2);
    asm volatile("cp.async.wait_group 2;\n" ::: "memory");
    __syncthreads();
    ldA(0, 0, af[0]); ldB(0, 0, bf[0]);

    for (int kt = 0; kt < KT; kt++) {
        int buf = kt & (NST - 1);

        // k32 step 0: prefetch step-1 frags, compute step-0
        ldA(buf, 32, af[1]); ldB(buf, 32, bf[1]);
        #pragma unroll
        for (int mb = 0; mb < 4; mb++)
            #pragma unroll
            for (int nb = 0; nb < 4; nb++)
                mma_s8(acc[mb][nb], af[0][mb], bf[0][nb]);

        // k32 step 1: advance pipeline, prefetch next stage's step-0 frags, compute step-1
        if (kt + 1 < KT) {
            if (kt + 3 < KT) load_stage((kt + 3) & (NST - 1), kt + 3);
            else asm volatile("cp.async.commit_group;\n");
            asm volatile("cp.async.wait_group 2;\n" ::: "memory");
            __syncthreads();
            int nbuf = (kt + 1) & (NST - 1);
            ldA(nbuf, 0, af[0]); ldB(nbuf, 0, bf[0]);
        }
        #pragma unroll
        for (int mb = 0; mb < 4; mb++)
            #pragma unroll
            for (int nb = 0; nb < 4; nb++)
                mma_s8(acc[mb][nb], af[1][mb], bf[1][nb]);
    }

    // ---- epilogue: dequant, logits, partial row-sums of exp, diag capture ----
    const float invt0 = s_invt0;

    #pragma unroll
    for (int mb = 0; mb < 4; mb++) {
        #pragma unroll
        for (int h = 0; h < 2; h++) {
            int rl = wm * 64 + mb * 16 + (lane >> 2) + 8 * h;
            int gi = rowBase + rl;
            float qa = s_qa[rl];
            float rs = 0.f;
            #pragma unroll
            for (int nb = 0; nb < 4; nb++) {
                #pragma unroll
                for (int p = 0; p < 2; p++) {
                    int cl = wn * 32 + nb * 8 + 2 * (lane & 3) + p;
                    int gj = colBase + cl;
                    float sv = (float)acc[mb][nb][h * 2 + p] * qa;
                    float l;
                    if (gj == gi) {
                        l = sv * s_qb[cl] * invt0;       // positive column uses t[0]
                        g_diag[scale][gi] = l;
                    } else {
                        l = sv * ((gj < gi) ? s_wlo[cl] : s_whi[cl]);
                    }
                    rs += __expf(l);
                }
            }
            rs += __shfl_xor_sync(0xffffffffu, rs, 1);
            rs += __shfl_xor_sync(0xffffffffu, rs, 2);
            if ((lane & 3) == 0) sred[rl][wn] = rs;
        }
    }
    __syncthreads();
    if (tid < BM) {
        float v = sred[tid][0] + sred[tid][1] + sred[tid][2] + sred[tid][3];
        g_partial[scale][bn][rowBase + tid] = v;   // written exactly once -> deterministic
    }
}

// ---------------- finalize: lse + weighted combine ----------------
__global__ __launch_bounds__(256) void finalize_kernel(float* out) {
    int i = blockIdx.x * 256 + threadIdx.x;
    const float wgt[3] = {1.f / 27.f, 1.f / 9.f, 1.f / 3.f};
    float accum = 0.f;
    #pragma unroll
    for (int s = 0; s < NSCALE; s++) {
        float sum = 0.f;
        #pragma unroll 8
        for (int bn = 0; bn < NBT; bn++) sum += g_partial[s][bn][i];
        accum += wgt[s] * (logf(sum) - g_diag[s][i]);
    }
    out[i] = accum;
}

// ---------------- host entry ----------------
extern "C" void kernel_launch(void* const* d_in, const int* in_sizes, int n_in,
                              void* d_out, int out_size) {
    Ptrs p{};
    const long KsArr[3] = {10000, 20000, 50000};
    int ni = 0;
    for (int i = 0; i < n_in; i++) {
        long sz = in_sizes[i];
        if (sz == (long)BSZ * DIM) {
            p.anchor = (const float*)d_in[i];
        } else if (sz == BSZ) {
            p.index = (const int*)d_in[i];
        } else if (sz == 100000) {
            if (ni < 3) p.i2c[ni++] = (const int*)d_in[i];
        } else {
            for (int s = 0; s < 3; s++) {
                if (sz == KsArr[s]) p.dens[s] = (const float*)d_in[i];
                else if (sz == KsArr[s] * (long)DIM) p.cent[s] = (const float*)d_in[i];
            }
        }
    }

    cudaFuncSetAttribute(gemm_kernel, cudaFuncAttributeMaxDynamicSharedMemorySize, SMEM_DYN);

    prep_kernel<<<(4 * BSZ) / 8, 256>>>(p);
    gemm_kernel<<<dim3(NBT, BSZ / BM, NSCALE), 256, SMEM_DYN>>>();
    finalize_kernel<<<BSZ / 256, 256>>>((float*)d_out);
}

// round 8
// speedup vs baseline: 2.4009x; 2.4009x over previous
#include <cuda_runtime.h>
#include <cuda_bf16.h>
#include <cstdint>

#define BSZ 4096
#define DIM 1024
#define NSCALE 3
#define BM 128
#define BN 128
#define BKK 32
#define NBT (BSZ / BN)      // 32 column tiles
#define KT (DIM / BKK)      // 32 k-stages
#define NST 4               // smem pipeline stages
#define PITCH 40            // bf16 elements per smem row (80 B) -> conflict-free ldmatrix
#define STAGE_B (BM * PITCH * 2)            // 10240 bytes per tile per stage
#define SMEM_DYN (2 * NST * STAGE_B)        // 81920

// ---------------- scratch (static device globals; no allocation) ----------------
__device__ __nv_bfloat16 g_A[BSZ * DIM];
__device__ __nv_bfloat16 g_P[NSCALE][BSZ * DIM];
__device__ float g_invt[NSCALE][BSZ];
__device__ float g_partial[NSCALE][NBT][BSZ];
__device__ float g_diag[NSCALE][BSZ];

struct Ptrs {
    const float* anchor;
    const int*   index;
    const int*   i2c[3];
    const float* cent[3];
    const float* dens[3];
};

// ---------------- PTX helpers ----------------
__device__ __forceinline__ uint32_t smem_u32(const void* p) {
    uint32_t a;
    asm("{ .reg .u64 t; cvta.to.shared.u64 t, %1; cvt.u32.u64 %0, t; }" : "=r"(a) : "l"(p));
    return a;
}
__device__ __forceinline__ void ldm_x4(uint32_t r[4], uint32_t addr) {
    asm volatile("ldmatrix.sync.aligned.m8n8.x4.shared.b16 {%0,%1,%2,%3}, [%4];\n"
                 : "=r"(r[0]), "=r"(r[1]), "=r"(r[2]), "=r"(r[3]) : "r"(addr));
}
__device__ __forceinline__ void mma16816(float c[4], const uint32_t a[4], const uint32_t b[2]) {
    asm volatile("mma.sync.aligned.m16n8k16.row.col.f32.bf16.bf16.f32 "
                 "{%0,%1,%2,%3}, {%4,%5,%6,%7}, {%8,%9}, {%0,%1,%2,%3};\n"
                 : "+f"(c[0]), "+f"(c[1]), "+f"(c[2]), "+f"(c[3])
                 : "r"(a[0]), "r"(a[1]), "r"(a[2]), "r"(a[3]), "r"(b[0]), "r"(b[1]));
}
__device__ __forceinline__ void cp16_s(uint32_t saddr, const void* gmem) {
    asm volatile("cp.async.cg.shared.global [%0], [%1], 16;\n" :: "r"(saddr), "l"(gmem));
}

// ---------------- prep: warp-per-row normalize to bf16 ----------------
__global__ __launch_bounds__(256) void prep_kernel(Ptrs p) {
    int w = blockIdx.x * 8 + (threadIdx.x >> 5);
    int lane = threadIdx.x & 31;

    const float* src;
    __nv_bfloat16* dst;
    if (w < BSZ) {
        src = p.anchor + (size_t)w * DIM;
        dst = g_A + (size_t)w * DIM;
    } else {
        int s = (w - BSZ) >> 12;
        int j = (w - BSZ) & (BSZ - 1);
        int cid = p.i2c[s][p.index[j]];
        src = p.cent[s] + (size_t)cid * DIM;
        dst = g_P[s] + (size_t)j * DIM;
        if (lane == 0) g_invt[s][j] = 1.0f / p.dens[s][cid];
    }

    float4 x[8];
    const float4* s4 = (const float4*)src;
    #pragma unroll
    for (int k = 0; k < 8; k++) x[k] = s4[lane + 32 * k];

    float ss = 0.f;
    #pragma unroll
    for (int k = 0; k < 8; k++)
        ss += x[k].x * x[k].x + x[k].y * x[k].y + x[k].z * x[k].z + x[k].w * x[k].w;
    #pragma unroll
    for (int o = 16; o > 0; o >>= 1) ss += __shfl_xor_sync(0xffffffffu, ss, o);
    float r = rsqrtf(fmaxf(ss, 1e-24f));

    __nv_bfloat162* d2 = (__nv_bfloat162*)dst;
    #pragma unroll
    for (int k = 0; k < 8; k++) {
        d2[2 * (lane + 32 * k)]     = __floats2bfloat162_rn(x[k].x * r, x[k].y * r);
        d2[2 * (lane + 32 * k) + 1] = __floats2bfloat162_rn(x[k].z * r, x[k].w * r);
    }
}

// ---------------- fused GEMM (S = A @ P^T) + exp epilogue, 4-stage, occ=2 ----------------
__global__ __launch_bounds__(256, 2) void gemm_kernel() {
    extern __shared__ char dynsmem[];
    const int scale = blockIdx.z;
    const int bm = blockIdx.y, bn = blockIdx.x;
    const int tid = threadIdx.x;
    const int lane = tid & 31;
    const int warp = tid >> 5;
    const int wm = warp >> 2;     // 0..1 : 64 rows each
    const int wn = warp & 3;      // 0..3 : 32 cols each

    __shared__ float sred[BM][4];
    __shared__ float s_invt[BN + 2];
    __shared__ float s_invt0;

    const uint32_t sAb = smem_u32(dynsmem);
    const uint32_t sBb = sAb + NST * STAGE_B;

    const __nv_bfloat16* gA = g_A + (size_t)(bm * BM) * DIM;
    const __nv_bfloat16* gB = g_P[scale] + (size_t)(bn * BN) * DIM;
    const float* invt = g_invt[scale];
    const int rowBase = bm * BM, colBase = bn * BN;

    if (tid <= BN) {
        int idx = colBase + tid;
        s_invt[tid] = invt[idx > BSZ - 1 ? BSZ - 1 : idx];
    }
    if (tid == 0) s_invt0 = invt[0];

    float acc[4][4][4];
    #pragma unroll
    for (int a = 0; a < 4; a++)
        #pragma unroll
        for (int b = 0; b < 4; b++)
            #pragma unroll
            for (int c = 0; c < 4; c++) acc[a][b][c] = 0.f;

    // ---- stage loader: 2x (A,B) 16B cp.async per thread per stage ----
    auto load_stage = [&](int buf, int kt) {
        uint32_t sa = sAb + buf * STAGE_B;
        uint32_t sb = sBb + buf * STAGE_B;
        const __nv_bfloat16* pA = gA + kt * BKK;
        const __nv_bfloat16* pB = gB + kt * BKK;
        #pragma unroll
        for (int r = 0; r < 2; r++) {
            int q = tid + 256 * r;
            int row = q >> 2, ch = q & 3;
            uint32_t off = (uint32_t)(row * (PITCH * 2) + ch * 16);
            cp16_s(sa + off, pA + (size_t)row * DIM + ch * 8);
            cp16_s(sb + off, pB + (size_t)row * DIM + ch * 8);
        }
        asm volatile("cp.async.commit_group;\n");
    };

    // prologue: fill 3 of 4 stages; stage 0 ready before loop entry
    load_stage(0, 0); load_stage(1, 1); load_stage(2, 2);
    asm volatile("cp.async.wait_group 2;\n" ::: "memory");
    __syncthreads();

    for (int kt = 0; kt < KT; kt++) {
        const int buf = kt & (NST - 1);
        const uint32_t aBase = sAb + buf * STAGE_B;
        const uint32_t bBase = sBb + buf * STAGE_B;

        #pragma unroll
        for (int kk = 0; kk < BKK; kk += 16) {
            uint32_t af[4][4], bf[4][2];
            #pragma unroll
            for (int mb = 0; mb < 4; mb++) {
                int row = wm * 64 + mb * 16 + (lane & 15);
                int ko = kk + ((lane & 16) ? 8 : 0);
                ldm_x4(af[mb], aBase + row * (PITCH * 2) + ko * 2);
            }
            #pragma unroll
            for (int nbp = 0; nbp < 2; nbp++) {
                int row = wn * 32 + nbp * 16 + (lane & 7) + ((lane & 16) ? 8 : 0);
                int ko = kk + ((lane & 8) ? 8 : 0);
                uint32_t t[4];
                ldm_x4(t, bBase + row * (PITCH * 2) + ko * 2);
                bf[nbp * 2][0] = t[0]; bf[nbp * 2][1] = t[1];
                bf[nbp * 2 + 1][0] = t[2]; bf[nbp * 2 + 1][1] = t[3];
            }
            #pragma unroll
            for (int mb = 0; mb < 4; mb++)
                #pragma unroll
                for (int nb = 0; nb < 4; nb++)
                    mma16816(acc[mb][nb], af[mb], bf[nb]);
        }

        // advance pipeline: stage (kt+3) overwrites buffer consumed at kt-1
        if (kt + 3 < KT) load_stage((kt + 3) & (NST - 1), kt + 3);
        else asm volatile("cp.async.commit_group;\n");
        asm volatile("cp.async.wait_group 2;\n" ::: "memory");
        __syncthreads();   // stage kt+1 visible to all; all warps done reading buf
    }

    // ---- epilogue: logits = s * w(col,row); partial row-sums of exp; diag capture ----
    const float invt0 = s_invt0;

    #pragma unroll
    for (int mb = 0; mb < 4; mb++) {
        #pragma unroll
        for (int h = 0; h < 2; h++) {
            int rl = wm * 64 + mb * 16 + (lane >> 2) + 8 * h;
            int gi = rowBase + rl;
            float rs = 0.f;
            #pragma unroll
            for (int nb = 0; nb < 4; nb++) {
                #pragma unroll
                for (int p = 0; p < 2; p++) {
                    int cl = wn * 32 + nb * 8 + 2 * (lane & 3) + p;
                    int gj = colBase + cl;
                    float sv = acc[mb][nb][h * 2 + p];
                    float l;
                    if (gj == gi) {
                        l = sv * invt0;              // positive column uses t[0]
                        g_diag[scale][gi] = l;
                    } else {
                        float w = (gj < gi) ? s_invt[cl + 1] : s_invt[cl];
                        l = sv * w;
                    }
                    rs += __expf(l);
                }
            }
            rs += __shfl_xor_sync(0xffffffffu, rs, 1);
            rs += __shfl_xor_sync(0xffffffffu, rs, 2);
            if ((lane & 3) == 0) sred[rl][wn] = rs;
        }
    }
    __syncthreads();
    if (tid < BM) {
        float v = sred[tid][0] + sred[tid][1] + sred[tid][2] + sred[tid][3];
        g_partial[scale][bn][rowBase + tid] = v;   // written exactly once -> deterministic
    }
}

// ---------------- finalize: lse + weighted combine ----------------
__global__ __launch_bounds__(256) void finalize_kernel(float* out) {
    int i = blockIdx.x * 256 + threadIdx.x;
    const float wgt[3] = {1.f / 27.f, 1.f / 9.f, 1.f / 3.f};
    float accum = 0.f;
    #pragma unroll
    for (int s = 0; s < NSCALE; s++) {
        float sum = 0.f;
        #pragma unroll 8
        for (int bn = 0; bn < NBT; bn++) sum += g_partial[s][bn][i];
        accum += wgt[s] * (logf(sum) - g_diag[s][i]);
    }
    out[i] = accum;
}

// ---------------- host entry ----------------
extern "C" void kernel_launch(void* const* d_in, const int* in_sizes, int n_in,
                              void* d_out, int out_size) {
    Ptrs p{};
    const long KsArr[3] = {10000, 20000, 50000};
    int ni = 0;
    for (int i = 0; i < n_in; i++) {
        long sz = in_sizes[i];
        if (sz == (long)BSZ * DIM) {
            p.anchor = (const float*)d_in[i];
        } else if (sz == BSZ) {
            p.index = (const int*)d_in[i];
        } else if (sz == 100000) {
            if (ni < 3) p.i2c[ni++] = (const int*)d_in[i];
        } else {
            for (int s = 0; s < 3; s++) {
                if (sz == KsArr[s]) p.dens[s] = (const float*)d_in[i];
                else if (sz == KsArr[s] * (long)DIM) p.cent[s] = (const float*)d_in[i];
            }
        }
    }

    cudaFuncSetAttribute(gemm_kernel, cudaFuncAttributeMaxDynamicSharedMemorySize, SMEM_DYN);

    prep_kernel<<<(4 * BSZ) / 8, 256>>>(p);
    gemm_kernel<<<dim3(NBT, BSZ / BM, NSCALE), 256, SMEM_DYN>>>();
    finalize_kernel<<<BSZ / 256, 256>>>((float*)d_out);
}

// round 10
// speedup vs baseline: 2.8996x; 1.2077x over previous
#include <cuda_runtime.h>
#include <cuda_bf16.h>
#include <cstdint>

#define BSZ 4096
#define DIM 1024
#define NSCALE 3
#define BM 128
#define BN 128
#define KSB 64              // bf16 K elements per stage (128 B of data per row)
#define KT16 (DIM / KSB)    // 16 stages
#define NBT (BSZ / BN)      // 32 column tiles
#define NST 3               // smem ring stages
#define STAGE_B (BM * 128)                  // 16384 bytes per tile per stage (SW128 rows)
#define SMEM_DYN (2 * NST * STAGE_B + 1024) // + alignment slack

#define SW128(off) ((off) ^ (((off) >> 3) & 0x70))

// ---------------- scratch (static device globals; no allocation) ----------------
__device__ __nv_bfloat16 g_A[BSZ * DIM];
__device__ __nv_bfloat16 g_P[NSCALE][BSZ * DIM];
__device__ float g_invt[NSCALE][BSZ];
__device__ float g_partial[NSCALE][NBT][BSZ];
__device__ float g_diag[NSCALE][BSZ];

struct Ptrs {
    const float* anchor;
    const int*   index;
    const int*   i2c[3];
    const float* cent[3];
    const float* dens[3];
};

// ---------------- PTX helpers ----------------
__device__ __forceinline__ uint32_t smem_u32(const void* p) {
    uint32_t a;
    asm("{ .reg .u64 t; cvta.to.shared.u64 t, %1; cvt.u32.u64 %0, t; }" : "=r"(a) : "l"(p));
    return a;
}
__device__ __forceinline__ void ldm_x4(uint32_t r[4], uint32_t addr) {
    asm volatile("ldmatrix.sync.aligned.m8n8.x4.shared.b16 {%0,%1,%2,%3}, [%4];\n"
                 : "=r"(r[0]), "=r"(r[1]), "=r"(r[2]), "=r"(r[3]) : "r"(addr));
}
__device__ __forceinline__ void mma16816(float c[4], const uint32_t a[4], const uint32_t b[2]) {
    asm volatile("mma.sync.aligned.m16n8k16.row.col.f32.bf16.bf16.f32 "
                 "{%0,%1,%2,%3}, {%4,%5,%6,%7}, {%8,%9}, {%0,%1,%2,%3};\n"
                 : "+f"(c[0]), "+f"(c[1]), "+f"(c[2]), "+f"(c[3])
                 : "r"(a[0]), "r"(a[1]), "r"(a[2]), "r"(a[3]), "r"(b[0]), "r"(b[1]));
}
__device__ __forceinline__ void cp16_s(uint32_t saddr, const void* gmem) {
    asm volatile("cp.async.cg.shared.global [%0], [%1], 16;\n" :: "r"(saddr), "l"(gmem));
}

// ---------------- prep: 2 rows per warp, normalize to bf16 ----------------
__global__ __launch_bounds__(256) void prep_kernel(Ptrs p) {
    int wbase = (blockIdx.x * 8 + (threadIdx.x >> 5)) * 2;
    int lane = threadIdx.x & 31;

    const float* src[2];
    __nv_bfloat16* dst[2];
    #pragma unroll
    for (int r = 0; r < 2; r++) {
        int w = wbase + r;
        if (w < BSZ) {
            src[r] = p.anchor + (size_t)w * DIM;
            dst[r] = g_A + (size_t)w * DIM;
        } else {
            int s = (w - BSZ) >> 12;
            int j = (w - BSZ) & (BSZ - 1);
            int cid = p.i2c[s][p.index[j]];
            src[r] = p.cent[s] + (size_t)cid * DIM;
            dst[r] = g_P[s] + (size_t)j * DIM;
            if (lane == (uint32_t)r) g_invt[s][j] = 1.0f / p.dens[s][cid];
        }
    }

    float4 x[2][8];
    #pragma unroll
    for (int k = 0; k < 8; k++) {
        x[0][k] = ((const float4*)src[0])[lane + 32 * k];
        x[1][k] = ((const float4*)src[1])[lane + 32 * k];
    }

    float ss0 = 0.f, ss1 = 0.f;
    #pragma unroll
    for (int k = 0; k < 8; k++) {
        ss0 += x[0][k].x * x[0][k].x + x[0][k].y * x[0][k].y + x[0][k].z * x[0][k].z + x[0][k].w * x[0][k].w;
        ss1 += x[1][k].x * x[1][k].x + x[1][k].y * x[1][k].y + x[1][k].z * x[1][k].z + x[1][k].w * x[1][k].w;
    }
    #pragma unroll
    for (int o = 16; o > 0; o >>= 1) {
        ss0 += __shfl_xor_sync(0xffffffffu, ss0, o);
        ss1 += __shfl_xor_sync(0xffffffffu, ss1, o);
    }
    float r0 = rsqrtf(fmaxf(ss0, 1e-24f));
    float r1 = rsqrtf(fmaxf(ss1, 1e-24f));

    __nv_bfloat162* d0 = (__nv_bfloat162*)dst[0];
    __nv_bfloat162* d1 = (__nv_bfloat162*)dst[1];
    #pragma unroll
    for (int k = 0; k < 8; k++) {
        d0[2 * (lane + 32 * k)]     = __floats2bfloat162_rn(x[0][k].x * r0, x[0][k].y * r0);
        d0[2 * (lane + 32 * k) + 1] = __floats2bfloat162_rn(x[0][k].z * r0, x[0][k].w * r0);
        d1[2 * (lane + 32 * k)]     = __floats2bfloat162_rn(x[1][k].x * r1, x[1][k].y * r1);
        d1[2 * (lane + 32 * k) + 1] = __floats2bfloat162_rn(x[1][k].z * r1, x[1][k].w * r1);
    }
}

// ---------------- fused GEMM (S = A @ P^T) + exp epilogue, 64-K SW128 stages, occ=2 ----------------
__global__ __launch_bounds__(256, 2) void gemm_kernel() {
    extern __shared__ char dynsmem[];
    const int scale = blockIdx.z;
    const int bm = blockIdx.y, bn = blockIdx.x;
    const int tid = threadIdx.x;
    const int lane = tid & 31;
    const int warp = tid >> 5;
    const int wm = warp >> 2;     // 0..1 : 64 rows each
    const int wn = warp & 3;      // 0..3 : 32 cols each

    __shared__ float sred[BM][4];
    __shared__ float s_invt[BN + 2];
    __shared__ float s_invt0;

    const uint32_t sAb = (smem_u32(dynsmem) + 1023u) & ~1023u;   // 1KB-align for SW128
    const uint32_t sBb = sAb + NST * STAGE_B;

    const __nv_bfloat16* gA = g_A + (size_t)(bm * BM) * DIM;
    const __nv_bfloat16* gB = g_P[scale] + (size_t)(bn * BN) * DIM;
    const float* invt = g_invt[scale];
    const int rowBase = bm * BM, colBase = bn * BN;

    if (tid <= BN) {
        int idx = colBase + tid;
        s_invt[tid] = invt[idx > BSZ - 1 ? BSZ - 1 : idx];
    }
    if (tid == 0) s_invt0 = invt[0];

    float acc[4][4][4];
    #pragma unroll
    for (int a = 0; a < 4; a++)
        #pragma unroll
        for (int b = 0; b < 4; b++)
            #pragma unroll
            for (int c = 0; c < 4; c++) acc[a][b][c] = 0.f;

    // ---- stage loader: 4x (A,B) 16B cp.async per thread per 64-K stage ----
    auto load_stage = [&](int buf, int kt) {
        uint32_t sa = sAb + buf * STAGE_B;
        uint32_t sb = sBb + buf * STAGE_B;
        const __nv_bfloat16* pA = gA + kt * KSB;
        const __nv_bfloat16* pB = gB + kt * KSB;
        #pragma unroll
        for (int r = 0; r < 4; r++) {
            int q = tid + 256 * r;                // 1024 16B chunks per tile
            int row = q >> 3, ch = q & 7;
            uint32_t off = SW128((uint32_t)(row * 128 + ch * 16));
            cp16_s(sa + off, pA + (size_t)row * DIM + ch * 8);
            cp16_s(sb + off, pB + (size_t)row * DIM + ch * 8);
        }
        asm volatile("cp.async.commit_group;\n");
    };

    // prologue: 2 stages in flight
    load_stage(0, 0); load_stage(1, 1);

    for (int kt = 0; kt < KT16; kt++) {
        if (kt + 1 < KT16) asm volatile("cp.async.wait_group 1;\n" ::: "memory");
        else               asm volatile("cp.async.wait_group 0;\n" ::: "memory");
        __syncthreads();                              // stage kt visible to all warps
        if (kt + 2 < KT16) load_stage((kt + 2) % NST, kt + 2);   // overlaps with compute below

        const int buf = kt % NST;
        const uint32_t aT = sAb + buf * STAGE_B;
        const uint32_t bT = sBb + buf * STAGE_B;

        const int aRow = wm * 64 + (lane & 15);
        const int aKo  = (lane & 16) ? 16 : 0;
        const int bRow = wn * 32 + (lane & 7) + ((lane & 16) ? 8 : 0);
        const int bKo  = (lane & 8) ? 16 : 0;

        #pragma unroll
        for (int kk = 0; kk < KSB; kk += 16) {
            uint32_t af[4][4], bf[4][2];
            #pragma unroll
            for (int mb = 0; mb < 4; mb++) {
                uint32_t off = SW128((uint32_t)((aRow + mb * 16) * 128 + kk * 2 + aKo));
                ldm_x4(af[mb], aT + off);
            }
            #pragma unroll
            for (int nbp = 0; nbp < 2; nbp++) {
                uint32_t off = SW128((uint32_t)((bRow + nbp * 16) * 128 + kk * 2 + bKo));
                uint32_t t[4];
                ldm_x4(t, bT + off);
                bf[nbp * 2][0] = t[0]; bf[nbp * 2][1] = t[1];
                bf[nbp * 2 + 1][0] = t[2]; bf[nbp * 2 + 1][1] = t[3];
            }
            #pragma unroll
            for (int mb = 0; mb < 4; mb++)
                #pragma unroll
                for (int nb = 0; nb < 4; nb++)
                    mma16816(acc[mb][nb], af[mb], bf[nb]);
        }
    }

    // ---- epilogue: logits = s * w(col,row); partial row-sums of exp; diag capture ----
    const float invt0 = s_invt0;

    #pragma unroll
    for (int mb = 0; mb < 4; mb++) {
        #pragma unroll
        for (int h = 0; h < 2; h++) {
            int rl = wm * 64 + mb * 16 + (lane >> 2) + 8 * h;
            int gi = rowBase + rl;
            float rs = 0.f;
            #pragma unroll
            for (int nb = 0; nb < 4; nb++) {
                #pragma unroll
                for (int p = 0; p < 2; p++) {
                    int cl = wn * 32 + nb * 8 + 2 * (lane & 3) + p;
                    int gj = colBase + cl;
                    float sv = acc[mb][nb][h * 2 + p];
                    float l;
                    if (gj == gi) {
                        l = sv * invt0;              // positive column uses t[0]
                        g_diag[scale][gi] = l;
                    } else {
                        float w = (gj < gi) ? s_invt[cl + 1] : s_invt[cl];
                        l = sv * w;
                    }
                    rs += __expf(l);
                }
            }
            rs += __shfl_xor_sync(0xffffffffu, rs, 1);
            rs += __shfl_xor_sync(0xffffffffu, rs, 2);
            if ((lane & 3) == 0) sred[rl][wn] = rs;
        }
    }
    __syncthreads();
    if (tid < BM) {
        float v = sred[tid][0] + sred[tid][1] + sred[tid][2] + sred[tid][3];
        g_partial[scale][bn][rowBase + tid] = v;   // written exactly once -> deterministic
    }
}

// ---------------- finalize: lse + weighted combine ----------------
__global__ __launch_bounds__(256) void finalize_kernel(float* out) {
    int i = blockIdx.x * 256 + threadIdx.x;
    const float wgt[3] = {1.f / 27.f, 1.f / 9.f, 1.f / 3.f};
    float accum = 0.f;
    #pragma unroll
    for (int s = 0; s < NSCALE; s++) {
        float sum = 0.f;
        #pragma unroll 8
        for (int bn = 0; bn < NBT; bn++) sum += g_partial[s][bn][i];
        accum += wgt[s] * (logf(sum) - g_diag[s][i]);
    }
    out[i] = accum;
}

// ---------------- host entry ----------------
extern "C" void kernel_launch(void* const* d_in, const int* in_sizes, int n_in,
                              void* d_out, int out_size) {
    Ptrs p{};
    const long KsArr[3] = {10000, 20000, 50000};
    int ni = 0;
    for (int i = 0; i < n_in; i++) {
        long sz = in_sizes[i];
        if (sz == (long)BSZ * DIM) {
            p.anchor = (const float*)d_in[i];
        } else if (sz == BSZ) {
            p.index = (const int*)d_in[i];
        } else if (sz == 100000) {
            if (ni < 3) p.i2c[ni++] = (const int*)d_in[i];
        } else {
            for (int s = 0; s < 3; s++) {
                if (sz == KsArr[s]) p.dens[s] = (const float*)d_in[i];
                else if (sz == KsArr[s] * (long)DIM) p.cent[s] = (const float*)d_in[i];
            }
        }
    }

    cudaFuncSetAttribute(gemm_kernel, cudaFuncAttributeMaxDynamicSharedMemorySize, SMEM_DYN);

    prep_kernel<<<(4 * BSZ) / 16, 256>>>(p);
    gemm_kernel<<<dim3(NBT, BSZ / BM, NSCALE), 256, SMEM_DYN>>>();
    finalize_kernel<<<BSZ / 256, 256>>>((float*)d_out);
}